// round 17
// baseline (speedup 1.0000x reference)
#include <cuda_runtime.h>

#define HF 64
#define WF 64
#define NPIX 4096
#define M_TOT 48
#define DCH 256
#define NGEMM 256   // gemm blocks at the front of k_main's grid

__device__ float g_A[M_TOT * NPIX];
__device__ float g_SA[M_TOT];
__device__ float g_WcT[DCH * DCH];    // WcT[c][o] = sum_k W_dc[o,k]*W_emb[k,c]
__device__ float g_bcomb[DCH];        // bcomb[o] = sum_k W_dc[o,k]*b_emb[k]
__device__ int   g_done;              // gemm completion counter

#define MAIN_SMEM (16*257*4 + 256*17*4 + 256*4)   // 34880 B (< 48KB, no attr needed)

// ---------------------------------------------------------------------------
// K_scatter: per-m flow downsample + bilinear weight scatter in shared.
// 48 blocks x 1024 threads, 4 dest pixels/thread. Also zeroes this m's out
// row and (block 0) resets the gemm completion counter for this launch.
// ---------------------------------------------------------------------------
__global__ void __launch_bounds__(1024) k_scatter(
    const float* __restrict__ pmot, float* __restrict__ out)
{
    int m = blockIdx.x;
    int tid = threadIdx.x;
    const float4* pm4 = reinterpret_cast<const float4*>(pmot + (size_t)m * 2u * 65536u);

    __shared__ float Ash[NPIX];
    __shared__ float partial[32];

    if (m == 0 && tid == 0) g_done = 0;
    if (tid < DCH) out[m * DCH + tid] = 0.f;

#pragma unroll
    for (int k = 0; k < 4; k++) Ash[k * 1024 + tid] = 0.f;
    __syncthreads();

    const float inv = 1.0f / 4096.0f;
#pragma unroll
    for (int k = 0; k < 4; k++) {
        int p = k * 1024 + tid;      // dest pixel 0..4095
        int i = p >> 6;
        int j = p & 63;

        const float4* ry1 = pm4 + (4 * i + 1) * 64 + j;
        const float4* ry2 = pm4 + (4 * i + 2) * 64 + j;
        float4 a0 = __ldg(ry1);
        float4 a1 = __ldg(ry2);
        float4 b0 = __ldg(ry1 + 16384);     // x-flow channel
        float4 b1 = __ldg(ry2 + 16384);

        float fy = (a0.y + a0.z + a1.y + a1.z) * 0.0625f;   // 2x2 avg * 0.25
        float fx = (b0.y + b0.z + b1.y + b1.z) * 0.0625f;

        float y = (float)i + fy;
        float x = (float)j + fx;
        float y0f = floorf(y), x0f = floorf(x);
        float wy = y - y0f, wx = x - x0f;
        int y0 = (int)y0f, x0 = (int)x0f;
        int y1 = y0 + 1, x1 = x0 + 1;

        float w00 = (1.f - wy) * (1.f - wx) * inv;
        float w01 = (1.f - wy) * wx * inv;
        float w10 = wy * (1.f - wx) * inv;
        float w11 = wy * wx * inv;

        bool vy0 = (y0 >= 0) & (y0 < HF);
        bool vy1 = (y1 >= 0) & (y1 < HF);
        bool vx0 = (x0 >= 0) & (x0 < WF);
        bool vx1 = (x1 >= 0) & (x1 < WF);

        if (vy0 & vx0) atomicAdd(&Ash[y0 * WF + x0], w00);
        if (vy0 & vx1) atomicAdd(&Ash[y0 * WF + x1], w01);
        if (vy1 & vx0) atomicAdd(&Ash[y1 * WF + x0], w10);
        if (vy1 & vx1) atomicAdd(&Ash[y1 * WF + x1], w11);
    }
    __syncthreads();

    // copy out + SA = sum(Ash)
    float4 v = reinterpret_cast<const float4*>(Ash)[tid];
    reinterpret_cast<float4*>(g_A)[m * 1024 + tid] = v;
    float s = v.x + v.y + v.z + v.w;
#pragma unroll
    for (int off = 16; off; off >>= 1)
        s += __shfl_down_sync(0xffffffffu, s, off);
    int warp = tid >> 5, lane = tid & 31;
    if (lane == 0) partial[warp] = s;
    __syncthreads();
    if (warp == 0) {
        float t = partial[lane];
#pragma unroll
        for (int off = 16; off; off >>= 1)
            t += __shfl_down_sync(0xffffffffu, t, off);
        if (lane == 0) g_SA[m] = t;
    }
}

// ---------------------------------------------------------------------------
// K_main: 1280 blocks x 256 threads, 34.9 KB dynamic smem.
//   bids 0..255    : Wcomb GEMM (16x16 tiles) + bcomb; publish via g_done.
//                    Guaranteed wave-1 (lowest bids) -> no deadlock.
//   bids 256..1279 : reduce (R16 shape: 4 channels x 3 m's, k-outer loop);
//                    main loop needs only g_A (ready: kernel boundary);
//                    epilogue spin-waits g_done==NGEMM (gemm ~3us, first
//                    epilogue ~10us -> spin is free), then Wcomb + atomics.
// ---------------------------------------------------------------------------
__global__ void __launch_bounds__(256, 4) k_main(
    const float* __restrict__ feat,
    const float* __restrict__ W_emb, const float* __restrict__ b_emb,
    const float* __restrict__ W_dc,  const float* __restrict__ b_dc,
    float* __restrict__ out)
{
    extern __shared__ char smem_raw[];
    int tid = threadIdx.x;

    if (blockIdx.x < NGEMM) {
        // ------------------- GEMM: WcT tile (16 o x 16 c) -------------------
        float* sA  = reinterpret_cast<float*>(smem_raw);     // [16][257]
        float* sB  = sA + 16 * 257;                          // [256][17]
        float* bsh = sB + 256 * 17;                          // [256]
        int bo = blockIdx.x & 15;
        int bc = blockIdx.x >> 4;
        int o0 = bo * 16, c0 = bc * 16;

#pragma unroll
        for (int e = 0; e < 16; e++) {
            int idx = e * 256 + tid;
            sA[(idx >> 8) * 257 + (idx & 255)] = W_dc[(o0 + (idx >> 8)) * DCH + (idx & 255)];
            sB[(idx >> 4) * 17 + (idx & 15)]   = W_emb[(idx >> 4) * DCH + c0 + (idx & 15)];
        }
        if (bc == 0) bsh[tid] = b_emb[tid];
        __syncthreads();

        int tx = tid & 15;        // o_local
        int ty = tid >> 4;        // c_local
        float acc = 0.f;
#pragma unroll 8
        for (int k = 0; k < 256; k++)
            acc += sA[tx * 257 + k] * sB[k * 17 + ty];
        g_WcT[(c0 + ty) * DCH + o0 + tx] = acc;

        if (bc == 0 && tid < 16) {
            float bacc = 0.f;
#pragma unroll 8
            for (int k = 0; k < 256; k++)
                bacc += sA[tid * 257 + k] * bsh[k];
            g_bcomb[o0 + tid] = bacc;
        }

        // publish
        __threadfence();
        __syncthreads();
        if (tid == 0) atomicAdd(&g_done, 1);
    } else {
        // ------------------- reduce: 4 channels x 3 m's -------------------
        int bid2 = blockIdx.x - NGEMM;
        int gf = bid2 >> 6;          // 0..15 == b*4+g
        int ct = bid2 & 63;          // 64 ctiles of 4 channels
        int b = gf >> 2, g = gf & 3;
        int m0 = b * 12 + g * 3;
        int warp = tid >> 5, lane = tid & 31;

        const float4* gA4 = reinterpret_cast<const float4*>(g_A) + m0 * 1024;
        const float4* F4 = reinterpret_cast<const float4*>(feat)
                         + (size_t)gf * DCH * 1024
                         + (size_t)ct * 4 * 1024;

        float acc[4][3];
#pragma unroll
        for (int ch = 0; ch < 4; ch++)
#pragma unroll
            for (int r = 0; r < 3; r++) acc[ch][r] = 0.f;

#pragma unroll
        for (int k = 0; k < 4; k++) {
            float4 a0 = gA4[0 * 1024 + k * 256 + tid];
            float4 a1 = gA4[1 * 1024 + k * 256 + tid];
            float4 a2 = gA4[2 * 1024 + k * 256 + tid];
            float4 f[4];
#pragma unroll
            for (int ch = 0; ch < 4; ch++)
                f[ch] = F4[ch * 1024 + k * 256 + tid];
#pragma unroll
            for (int ch = 0; ch < 4; ch++) {
                acc[ch][0] += a0.x * f[ch].x + a0.y * f[ch].y + a0.z * f[ch].z + a0.w * f[ch].w;
                acc[ch][1] += a1.x * f[ch].x + a1.y * f[ch].y + a1.z * f[ch].z + a1.w * f[ch].w;
                acc[ch][2] += a2.x * f[ch].x + a2.y * f[ch].y + a2.z * f[ch].z + a2.w * f[ch].w;
            }
        }

        float* red  = reinterpret_cast<float*>(smem_raw);   // [4*256*3]
        float* sacc = red + 4 * 256 * 3;                    // [3][4]
#pragma unroll
        for (int ch = 0; ch < 4; ch++) {
            float* rp = &red[ch * 768 + tid * 3];
            rp[0] = acc[ch][0];
            rp[1] = acc[ch][1];
            rp[2] = acc[ch][2];
        }
        __syncthreads();

        if (warp < 4) {
#pragma unroll
            for (int r = 0; r < 3; r++) {
                float s = 0.f;
#pragma unroll
                for (int k = 0; k < 8; k++)
                    s += red[warp * 768 + (lane + k * 32) * 3 + r];
#pragma unroll
                for (int off = 16; off; off >>= 1)
                    s += __shfl_down_sync(0xffffffffu, s, off);
                if (lane == 0) sacc[r * 4 + warp] = s;
            }
        }

        // wait for gemm results (usually already done)
        if (tid == 0) {
            while (atomicAdd(&g_done, 0) < NGEMM) __nanosleep(32);
            __threadfence();
        }
        __syncthreads();

        // Wcomb epilogue: thread = output channel o
        {
            int o = tid;
            int c0 = ct * 4;
            float v0 = 0.f, v1 = 0.f, v2 = 0.f;
#pragma unroll
            for (int ch = 0; ch < 4; ch++) {
                float wv = g_WcT[(c0 + ch) * DCH + o];
                v0 += wv * sacc[0 * 4 + ch];
                v1 += wv * sacc[1 * 4 + ch];
                v2 += wv * sacc[2 * 4 + ch];
            }
            if (ct == 0) {
                float bc2 = g_bcomb[o];
                float bd = b_dc[o];
                v0 += g_SA[m0 + 0] * bc2 + bd;
                v1 += g_SA[m0 + 1] * bc2 + bd;
                v2 += g_SA[m0 + 2] * bc2 + bd;
            }
            atomicAdd(&out[(m0 + 0) * DCH + o], v0);
            atomicAdd(&out[(m0 + 1) * DCH + o], v1);
            atomicAdd(&out[(m0 + 2) * DCH + o], v2);
        }
    }
}

// ---------------------------------------------------------------------------
// inputs (metadata order): imgs, i_features, p_motions, W_emb, b_emb, W_dc, b_dc
// output: float32 [4,4,3,256] = 12288 elements
// ---------------------------------------------------------------------------
extern "C" void kernel_launch(void* const* d_in, const int* in_sizes, int n_in,
                              void* d_out, int out_size) {
    const float* i_features = (const float*)d_in[1];
    const float* p_motions  = (const float*)d_in[2];
    const float* W_emb      = (const float*)d_in[3];
    const float* b_emb      = (const float*)d_in[4];
    const float* W_dc       = (const float*)d_in[5];
    const float* b_dc       = (const float*)d_in[6];
    float* out = (float*)d_out;

    k_scatter<<<48, 1024>>>(p_motions, out);
    k_main<<<NGEMM + 1024, 256, MAIN_SMEM>>>(i_features, W_emb, b_emb, W_dc, b_dc, out);
}